// round 14
// baseline (speedup 1.0000x reference)
#include <cuda_runtime.h>
#include <cuda_fp16.h>
#include <cstdint>

// ----------------------------------------------------------------------------
// LinearMultiHeadAttention, fully reassociated (fp16 mma.sync, fp32 accum):
//   G_b  = x_b^T x_b          (symmetric: 36 lower-tri blocks, split-K x2)
//   T1_b = Wk @ G_b           (GEMM, 1024^3)
//   kv[b,h] = 0.125 * T1_h @ Wv_h^T   (fp32, split-K8 + reduce)
//   Zt_b[n][hd] = sum_e Wo[n][he] kv[b,h,d,e]
//   Pt_b = Zt_b @ Wq_t^T      (GEMM, 1024^3)
//   out_b = x_b @ Pt_b^T      (GEMM, M=4096, N=K=1024, fp32 out)
// R14: LDGSTS de-bursting — the per-K-tile cp.async prefetch (16 instrs/warp)
//      is split into 4 parts issued between the ks MMA blocks, so the LSU
//      issue cost overlaps tensor work instead of stalling the loop head.
//      Plus Wk/Wv converts fused into one dual launch.
// ----------------------------------------------------------------------------

static constexpr int BATCH  = 4;
static constexpr int SEQ    = 4096;
static constexpr int DMODEL = 1024;
static constexpr int HEADS  = 16;
static constexpr int DKH    = 64;
static constexpr int NTOK   = BATCH * SEQ;   // 16384
static constexpr int NTRI   = 36;            // lower-triangle 128x128 blocks

// Scratch (__device__ globals; no allocations allowed)
__device__ __half g_xt[NTOK * DMODEL];                 // x fp16 [b][t][c]
__device__ __half g_xT[NTOK * DMODEL];                 // x fp16 [b][c][t]
__device__ __half g_wk[DMODEL * DMODEL];
__device__ __half g_wv[DMODEL * DMODEL];
__device__ __half g_wqt[DMODEL * DMODEL];              // Wq^T [c][hd]
__device__ float  g_gpart[2 * BATCH * NTRI * 128 * 128];   // 18 MB
__device__ __half g_G[BATCH * DMODEL * DMODEL];
__device__ __half g_t1[BATCH * DMODEL * DMODEL];
__device__ float  g_kvp[8 * BATCH * HEADS * DKH * DKH];
__device__ float  g_kv[BATCH * HEADS * DKH * DKH];
__device__ __half g_zt[BATCH * DMODEL * DMODEL];
__device__ __half g_pt[BATCH * DMODEL * DMODEL];

// ------------------------------------------------------------------ helpers --
__device__ __forceinline__ void cp16(uint32_t smem_dst, const void* gmem_src) {
    asm volatile("cp.async.cg.shared.global [%0], [%1], 16;"
                 :: "r"(smem_dst), "l"(gmem_src) : "memory");
}
__device__ __forceinline__ uint32_t smem_u32(const void* p) {
    uint32_t a;
    asm("{ .reg .u64 t; cvta.to.shared.u64 t, %1; cvt.u32.u64 %0, t; }"
        : "=r"(a) : "l"(p));
    return a;
}
__device__ __forceinline__ void ldsm4(uint32_t& r0, uint32_t& r1,
                                      uint32_t& r2, uint32_t& r3,
                                      uint32_t addr) {
    asm volatile("ldmatrix.sync.aligned.m8n8.x4.shared.b16 {%0,%1,%2,%3}, [%4];"
                 : "=r"(r0), "=r"(r1), "=r"(r2), "=r"(r3) : "r"(addr));
}
__device__ __forceinline__ void store_pair(float* C, float a, float b) {
    *(float2*)C = make_float2(a, b);
}
__device__ __forceinline__ void store_pair(__half* C, float a, float b) {
    *(__half2*)C = __floats2half2_rn(a, b);
}

// --------------------------------------------------------------- converts ---
__global__ void f32_to_f16_dual(const float* __restrict__ s0,
                                const float* __restrict__ s1,
                                __half* __restrict__ d0,
                                __half* __restrict__ d1, int n4) {
    const float* s = blockIdx.y ? s1 : s0;
    __half* d = blockIdx.y ? d1 : d0;
    int i = blockIdx.x * blockDim.x + threadIdx.x;
    int stride = gridDim.x * blockDim.x;
    for (; i < n4; i += stride) {
        float4 v = ((const float4*)s)[i];
        __half2* o = (__half2*)d + 2 * (size_t)i;
        o[0] = __floats2half2_rn(v.x, v.y);
        o[1] = __floats2half2_rn(v.z, v.w);
    }
}

// x fp32 [b][t][c] -> xt fp16 [b][t][c] AND xT fp16 [b][c][t]
__global__ void convert_transpose_x(const float* __restrict__ x,
                                    __half* __restrict__ xt,
                                    __half* __restrict__ xT) {
    __shared__ __half tile[32][33];
    const int c0 = blockIdx.x * 32;
    const int t0 = blockIdx.y * 32;
    const int tx = threadIdx.x & 31;
    const int ty = threadIdx.x >> 5;
    #pragma unroll
    for (int i = 0; i < 4; i++) {
        int t = t0 + ty + i * 8;
        __half h = __float2half_rn(x[(size_t)t * DMODEL + c0 + tx]);
        xt[(size_t)t * DMODEL + c0 + tx] = h;
        tile[ty + i * 8][tx] = h;
    }
    __syncthreads();
    const int b = t0 >> 12;
    const int tl = t0 & 4095;
    #pragma unroll
    for (int i = 0; i < 4; i++) {
        int c = c0 + ty + i * 8;
        xT[((size_t)b * DMODEL + c) * SEQ + tl + tx] = tile[tx][ty + i * 8];
    }
}

// W fp32 [r][c] (1024x1024) -> Wt fp16 [c][r]
__global__ void convert_transpose_w(const float* __restrict__ W,
                                    __half* __restrict__ Wt) {
    __shared__ __half tile[32][33];
    const int c0 = blockIdx.x * 32;
    const int r0 = blockIdx.y * 32;
    const int tx = threadIdx.x & 31;
    const int ty = threadIdx.x >> 5;
    #pragma unroll
    for (int i = 0; i < 4; i++) {
        int r = r0 + ty + i * 8;
        tile[ty + i * 8][tx] = __float2half_rn(W[(size_t)r * DMODEL + c0 + tx]);
    }
    __syncthreads();
    #pragma unroll
    for (int i = 0; i < 4; i++) {
        int c = c0 + ty + i * 8;
        Wt[(size_t)c * DMODEL + r0 + tx] = tile[tx][ty + i * 8];
    }
}

// --------------------------------------------------------- GEMM constants ---
// K-tile 64 halves = 128B rows, SW128 XOR swizzle.
// Stage = A(128x128B) + B(128x128B) = 32768 B; 3 stages = 98304 B dynamic.
static constexpr int KT      = 64;
static constexpr int STG_B   = 32768;
static constexpr int B_OFF   = 16384;
static constexpr int NSTG    = 3;
static constexpr int GEMM_SMEM = NSTG * STG_B;   // 98304
static constexpr int GEMM_THREADS = 128;         // 4 warps (2x2), warp 64x64

// Mainloop: CTA 128x128, warp 64x64. 3-stage cp.async, one barrier per K-tile.
// cp.async prefetch split into 4 parts, one issued per ks block (de-bursted
// LDGSTS). Fragments double-buffered. Fills c[4][8][4].
struct FragAddr {
    uint32_t arow[4], brow[4];
    uint32_t asw[4], bsw[4];
    uint32_t lcolb;
};

#define GEMM_MAINLOOP(Ab, Bb, lda, ldb, nkt)                                   \
    const uint32_t sb = smem_u32(sm);                                          \
    auto prefetch_part = [&](int kt, int p) {                                  \
        uint32_t stg = sb + (kt % NSTG) * STG_B;                               \
        _Pragma("unroll")                                                      \
        for (int i = 2 * p; i < 2 * p + 2; i++) {                              \
            int idx = tid + i * 128;                                           \
            int row = idx >> 3, cc = idx & 7;                                  \
            uint32_t sw = (uint32_t)(cc * 16) ^ (uint32_t)((row & 7) << 4);    \
            cp16(stg + row * 128 + sw,                                         \
                 (Ab) + (size_t)row * (lda) + kt * KT + cc * 8);               \
            cp16(stg + B_OFF + row * 128 + sw,                                 \
                 (Bb) + (size_t)row * (ldb) + kt * KT + cc * 8);               \
        }                                                                      \
    };                                                                         \
    auto prefetch = [&](int kt) {                                              \
        prefetch_part(kt, 0); prefetch_part(kt, 1);                            \
        prefetch_part(kt, 2); prefetch_part(kt, 3);                            \
        asm volatile("cp.async.commit_group;" ::: "memory");                   \
    };                                                                         \
    prefetch(0);                                                               \
    prefetch(1);                                                               \
    float c[4][8][4];                                                          \
    _Pragma("unroll")                                                          \
    for (int i = 0; i < 4; i++)                                                \
        _Pragma("unroll")                                                      \
        for (int j = 0; j < 8; j++)                                            \
            _Pragma("unroll")                                                  \
            for (int k = 0; k < 4; k++) c[i][j][k] = 0.f;                      \
    const int lrow = (lane & 7) + ((lane >> 3) & 1) * 8;                       \
    FragAddr fa;                                                               \
    fa.lcolb = (uint32_t)((lane >> 4) * 16);                                   \
    _Pragma("unroll")                                                          \
    for (int fm = 0; fm < 4; fm++) {                                           \
        int r = wm + fm * 16 + lrow;                                           \
        fa.arow[fm] = (uint32_t)(r * 128);                                     \
        fa.asw[fm]  = (uint32_t)((r & 7) << 4);                                \
    }                                                                          \
    _Pragma("unroll")                                                          \
    for (int fp = 0; fp < 4; fp++) {                                           \
        int r = wn + fp * 16 + lrow;                                           \
        fa.brow[fp] = (uint32_t)(B_OFF + r * 128);                             \
        fa.bsw[fp]  = (uint32_t)((r & 7) << 4);                                \
    }                                                                          \
    uint32_t afr[2][4][4], bfr[2][8][2];                                       \
    auto ldfrag = [&](uint32_t stg, int ks, int buf) {                         \
        const uint32_t cb = (uint32_t)(ks * 32) + fa.lcolb;                    \
        _Pragma("unroll")                                                      \
        for (int fm = 0; fm < 4; fm++)                                         \
            ldsm4(afr[buf][fm][0], afr[buf][fm][1],                            \
                  afr[buf][fm][2], afr[buf][fm][3],                            \
                  stg + fa.arow[fm] + (cb ^ fa.asw[fm]));                      \
        _Pragma("unroll")                                                      \
        for (int fp = 0; fp < 4; fp++) {                                       \
            uint32_t t0, t1, t2, t3;                                           \
            ldsm4(t0, t1, t2, t3, stg + fa.brow[fp] + (cb ^ fa.bsw[fp]));      \
            bfr[buf][2 * fp][0] = t0;      bfr[buf][2 * fp][1] = t2;           \
            bfr[buf][2 * fp + 1][0] = t1;  bfr[buf][2 * fp + 1][1] = t3;       \
        }                                                                      \
    };                                                                         \
    for (int kt = 0; kt < (nkt); kt++) {                                       \
        if (kt + 1 < (nkt)) asm volatile("cp.async.wait_group 1;" ::: "memory"); \
        else                asm volatile("cp.async.wait_group 0;" ::: "memory"); \
        __syncthreads();                                                       \
        const uint32_t stg = sb + (kt % NSTG) * STG_B;                         \
        const bool pf = (kt + 2 < (nkt));                                      \
        ldfrag(stg, 0, 0);                                                     \
        _Pragma("unroll")                                                      \
        for (int ks = 0; ks < 4; ks++) {                                       \
            const int cur = ks & 1;                                            \
            if (pf) prefetch_part(kt + 2, ks);                                 \
            if (ks < 3) ldfrag(stg, ks + 1, cur ^ 1);                          \
            _Pragma("unroll")                                                  \
            for (int fm = 0; fm < 4; fm++)                                     \
                _Pragma("unroll")                                              \
                for (int fn = 0; fn < 8; fn++)                                 \
                    asm volatile(                                              \
                        "mma.sync.aligned.m16n8k16.row.col.f32.f16.f16.f32 "   \
                        "{%0,%1,%2,%3},{%4,%5,%6,%7},{%8,%9},{%0,%1,%2,%3};"   \
                        : "+f"(c[fm][fn][0]), "+f"(c[fm][fn][1]),              \
                          "+f"(c[fm][fn][2]), "+f"(c[fm][fn][3])               \
                        : "r"(afr[cur][fm][0]), "r"(afr[cur][fm][1]),          \
                          "r"(afr[cur][fm][2]), "r"(afr[cur][fm][3]),          \
                          "r"(bfr[cur][fn][0]), "r"(bfr[cur][fn][1]));         \
        }                                                                      \
        if (pf) asm volatile("cp.async.commit_group;" ::: "memory");           \
    }

// --------------------------------------------------- G = x^T x (sym+splitK) --
__global__ __launch_bounds__(GEMM_THREADS, 2)
void gemm_gsym(const __half* __restrict__ xT, float* __restrict__ gpart) {
    extern __shared__ __half sm[];
    const int tid  = threadIdx.x;
    const int lane = tid & 31;
    const int warp = tid >> 5;
    const int wm   = (warp >> 1) * 64;
    const int wn   = (warp & 1) * 64;

    const int tri = blockIdx.y;
    int bi = 0;
    while ((bi + 1) * (bi + 2) / 2 <= tri) bi++;
    const int bj = tri - bi * (bi + 1) / 2;

    const __half* Ab = xT + ((size_t)blockIdx.z * DMODEL + bi * 128) * SEQ
                          + blockIdx.x * 2048;
    const __half* Bb = xT + ((size_t)blockIdx.z * DMODEL + bj * 128) * SEQ
                          + blockIdx.x * 2048;
    float* Cb = gpart + (((size_t)blockIdx.x * BATCH + blockIdx.z) * NTRI + tri)
                        * (128 * 128);

    GEMM_MAINLOOP(Ab, Bb, SEQ, SEQ, 2048 / KT)

    #pragma unroll
    for (int fm = 0; fm < 4; fm++) {
        int r = wm + fm * 16 + (lane >> 2);
        #pragma unroll
        for (int fn = 0; fn < 8; fn++) {
            int cc = wn + fn * 8 + (lane & 3) * 2;
            store_pair(Cb + (size_t)r * 128 + cc,       c[fm][fn][0], c[fm][fn][1]);
            store_pair(Cb + (size_t)(r + 8) * 128 + cc, c[fm][fn][2], c[fm][fn][3]);
        }
    }
}

// Reduce the 2 K-partials, write G tile and (off-diagonal) its mirror.
__global__ void g_reduce_mirror(const float* __restrict__ gpart,
                                __half* __restrict__ G) {
    const int tri = blockIdx.x, b = blockIdx.y;
    int bi = 0;
    while ((bi + 1) * (bi + 2) / 2 <= tri) bi++;
    const int bj = tri - bi * (bi + 1) / 2;

    const float* p0 = gpart + (((size_t)0 * BATCH + b) * NTRI + tri) * (128 * 128);
    const float* p1 = gpart + (((size_t)1 * BATCH + b) * NTRI + tri) * (128 * 128);
    __half* Gb = G + (size_t)b * DMODEL * DMODEL;

    __shared__ __half tr[32][33];
    const int tid = threadIdx.x;
    const int r  = tid >> 3;
    const int cq = (tid & 7) * 4;

    for (int st = 0; st < 16; st++) {
        const int sr = (st >> 2) * 32, sc = (st & 3) * 32;
        __half h[4];
        #pragma unroll
        for (int i = 0; i < 4; i++) {
            int idx = (sr + r) * 128 + sc + cq + i;
            h[i] = __float2half_rn(p0[idx] + p1[idx]);
        }
        {
            __half* o = Gb + (size_t)(bi * 128 + sr + r) * DMODEL
                            + bj * 128 + sc + cq;
            ((__half2*)o)[0] = __halves2half2(h[0], h[1]);
            ((__half2*)o)[1] = __halves2half2(h[2], h[3]);
        }
        __syncthreads();
        #pragma unroll
        for (int i = 0; i < 4; i++) tr[cq + i][r] = h[i];
        __syncthreads();
        if (bi != bj) {
            __half m0 = tr[r][cq], m1 = tr[r][cq + 1];
            __half m2 = tr[r][cq + 2], m3 = tr[r][cq + 3];
            __half* o = Gb + (size_t)(bj * 128 + sc + r) * DMODEL
                            + bi * 128 + sr + cq;
            ((__half2*)o)[0] = __halves2half2(m0, m1);
            ((__half2*)o)[1] = __halves2half2(m2, m3);
        }
    }
}

// ----------------------------------------------------------- fp16 GEMM ------
template <typename OutT>
__global__ __launch_bounds__(GEMM_THREADS, 2)
void gemm_f16c(const __half* __restrict__ A, const __half* __restrict__ B,
               OutT* __restrict__ C, int lda, int ldb, int ldc, int nkt,
               size_t abatch, size_t bbatch, size_t cbatch) {
    extern __shared__ __half sm[];
    const int tid  = threadIdx.x;
    const int lane = tid & 31;
    const int warp = tid >> 5;
    const int wm   = (warp >> 1) * 64;
    const int wn   = (warp & 1) * 64;
    const int m0   = blockIdx.y * 128;
    const int n0   = blockIdx.x * 128;
    const int zz   = blockIdx.z;

    const __half* Ab = A + zz * abatch + (size_t)m0 * lda;
    const __half* Bb = B + zz * bbatch + (size_t)n0 * ldb;
    OutT*         Cb = C + zz * cbatch;

    GEMM_MAINLOOP(Ab, Bb, lda, ldb, nkt)

    #pragma unroll
    for (int fm = 0; fm < 4; fm++) {
        int r = m0 + wm + fm * 16 + (lane >> 2);
        #pragma unroll
        for (int fn = 0; fn < 8; fn++) {
            int cc = n0 + wn + fn * 8 + (lane & 3) * 2;
            store_pair(Cb + (size_t)r * ldc + cc,       c[fm][fn][0], c[fm][fn][1]);
            store_pair(Cb + (size_t)(r + 8) * ldc + cc, c[fm][fn][2], c[fm][fn][3]);
        }
    }
}

// ----------------------------------------------- kv from T1 (split-K x8) ----
__global__ void kv_from_t1_part(const __half* __restrict__ T1,
                                const __half* __restrict__ Wv,
                                float* __restrict__ kvp) {
    const int ck = blockIdx.x, h = blockIdx.y, b = blockIdx.z;
    const int tid = threadIdx.x;
    __shared__ float t1s[64][36];
    __shared__ float wvs[64][36];

    const int row = tid >> 2;
    const int seg = (tid & 3) * 8;
    const int td  = (tid >> 4) * 4;
    const int te  = (tid & 15) * 4;

    const __half* t1b = T1 + ((size_t)b * DMODEL + h * DKH) * DMODEL;
    const __half* wvb = Wv + (size_t)(h * DKH) * DMODEL;

    float acc[4][4];
    #pragma unroll
    for (int i = 0; i < 4; i++)
        #pragma unroll
        for (int j = 0; j < 4; j++) acc[i][j] = 0.f;

    const int cbeg = ck * 128;
    for (int c0 = cbeg; c0 < cbeg + 128; c0 += 32) {
        #pragma unroll
        for (int u = 0; u < 4; u++) {
            float2 f = __half22float2(
                *(const __half2*)(t1b + (size_t)row * DMODEL + c0 + seg + 2 * u));
            t1s[row][seg + 2 * u]     = f.x;
            t1s[row][seg + 2 * u + 1] = f.y;
            float2 g = __half22float2(
                *(const __half2*)(wvb + (size_t)row * DMODEL + c0 + seg + 2 * u));
            wvs[row][seg + 2 * u]     = g.x;
            wvs[row][seg + 2 * u + 1] = g.y;
        }
        __syncthreads();
        #pragma unroll
        for (int kk = 0; kk < 32; kk++) {
            float a0 = t1s[td + 0][kk], a1 = t1s[td + 1][kk];
            float a2 = t1s[td + 2][kk], a3 = t1s[td + 3][kk];
            float b0 = wvs[te + 0][kk], b1 = wvs[te + 1][kk];
            float b2 = wvs[te + 2][kk], b3 = wvs[te + 3][kk];
            acc[0][0] += a0 * b0; acc[0][1] += a0 * b1;
            acc[0][2] += a0 * b2; acc[0][3] += a0 * b3;
            acc[1][0] += a1 * b0; acc[1][1] += a1 * b1;
            acc[1][2] += a1 * b2; acc[1][3] += a1 * b3;
            acc[2][0] += a2 * b0; acc[2][1] += a2 * b1;
            acc[2][2] += a2 * b2; acc[2][3] += a2 * b3;
            acc[3][0] += a3 * b0; acc[3][1] += a3 * b1;
            acc[3][2] += a3 * b2; acc[3][3] += a3 * b3;
        }
        __syncthreads();
    }

    float* o = kvp + ((size_t)(ck * BATCH * HEADS) + b * HEADS + h) * (DKH * DKH);
    #pragma unroll
    for (int i = 0; i < 4; i++)
        *(float4*)(o + (size_t)(td + i) * DKH + te) =
            make_float4(acc[i][0], acc[i][1], acc[i][2], acc[i][3]);
}

__global__ void kv_reduce_kernel(const float* __restrict__ kvp,
                                 float* __restrict__ kv) {
    int idx = blockIdx.x * blockDim.x + threadIdx.x;
    const size_t stride = (size_t)BATCH * HEADS * DKH * DKH;
    float s = 0.f;
    #pragma unroll
    for (int ck = 0; ck < 8; ck++) s += kvp[ck * stride + idx];
    kv[idx] = s * 0.125f;
}

// -------------------------------------------------------------- Z build -----
__global__ void zbuild_kernel(const float* __restrict__ kv,
                              const float* __restrict__ Wo,
                              __half* __restrict__ zt) {
    const int nb = blockIdx.x, h = blockIdx.y, b = blockIdx.z;
    const int tid = threadIdx.x;
    __shared__ float wos[64][64];
    __shared__ float kvs[64][64];

    {
        const int r = tid >> 2;
        const int c0 = (tid & 3) * 16;
        const float* wsrc = Wo + (size_t)(nb * 64 + r) * DMODEL + h * DKH;
        const float* ksrc = kv + (size_t)((b * HEADS + h) * DKH + r) * DKH;
        #pragma unroll
        for (int i = 0; i < 4; i++) {
            *(float4*)&wos[r][c0 + i * 4] = *(const float4*)(wsrc + c0 + i * 4);
            *(float4*)&kvs[r][c0 + i * 4] = *(const float4*)(ksrc + c0 + i * 4);
        }
    }
    __syncthreads();

    const int tn = (tid >> 4) * 4;
    const int td = (tid & 15) * 4;
    float acc[4][4];
    #pragma unroll
    for (int i = 0; i < 4; i++)
        #pragma unroll
        for (int j = 0; j < 4; j++) acc[i][j] = 0.f;

    for (int e = 0; e < 64; e += 4) {
        float4 w[4], k[4];
        #pragma unroll
        for (int i = 0; i < 4; i++) w[i] = *(const float4*)&wos[tn + i][e];
        #pragma unroll
        for (int j = 0; j < 4; j++) k[j] = *(const float4*)&kvs[td + j][e];
        #pragma unroll
        for (int i = 0; i < 4; i++)
            #pragma unroll
            for (int j = 0; j < 4; j++)
                acc[i][j] += w[i].x * k[j].x + w[i].y * k[j].y +
                             w[i].z * k[j].z + w[i].w * k[j].w;
    }

    #pragma unroll
    for (int i = 0; i < 4; i++) {
        __half* o = zt + (size_t)(b * DMODEL + nb * 64 + tn + i) * DMODEL
                       + h * DKH + td;
        ((__half2*)o)[0] = __floats2half2_rn(acc[i][0], acc[i][1]);
        ((__half2*)o)[1] = __floats2half2_rn(acc[i][2], acc[i][3]);
    }
}

// -------------------------------------------------------------------- launch --
extern "C" void kernel_launch(void* const* d_in, const int* in_sizes, int n_in,
                              void* d_out, int out_size) {
    (void)in_sizes; (void)n_in; (void)out_size;
    const float* x  = (const float*)d_in[0];
    const float* Wq = (const float*)d_in[1];
    const float* Wk = (const float*)d_in[2];
    const float* Wv = (const float*)d_in[3];
    const float* Wo = (const float*)d_in[4];
    float* out = (float*)d_out;

    __half *xt, *xT, *wk, *wv, *wqt, *G, *t1, *zt, *pt;
    float *gpart, *kvp, *kv;
    cudaGetSymbolAddress((void**)&xt,    g_xt);
    cudaGetSymbolAddress((void**)&xT,    g_xT);
    cudaGetSymbolAddress((void**)&wk,    g_wk);
    cudaGetSymbolAddress((void**)&wv,    g_wv);
    cudaGetSymbolAddress((void**)&wqt,   g_wqt);
    cudaGetSymbolAddress((void**)&gpart, g_gpart);
    cudaGetSymbolAddress((void**)&G,     g_G);
    cudaGetSymbolAddress((void**)&t1,    g_t1);
    cudaGetSymbolAddress((void**)&kvp,   g_kvp);
    cudaGetSymbolAddress((void**)&kv,    g_kv);
    cudaGetSymbolAddress((void**)&zt,    g_zt);
    cudaGetSymbolAddress((void**)&pt,    g_pt);

    cudaFuncSetAttribute(gemm_gsym,
                         cudaFuncAttributeMaxDynamicSharedMemorySize, GEMM_SMEM);
    cudaFuncSetAttribute(gemm_f16c<__half>,
                         cudaFuncAttributeMaxDynamicSharedMemorySize, GEMM_SMEM);
    cudaFuncSetAttribute(gemm_f16c<float>,
                         cudaFuncAttributeMaxDynamicSharedMemorySize, GEMM_SMEM);

    const size_t DD = (size_t)DMODEL * DMODEL;

    // 1-3) converts needed by G (G GEMM stays launch #4 for ncu A/B comparison)
    convert_transpose_x<<<dim3(DMODEL / 32, NTOK / 32), 256>>>(x, xt, xT);
    f32_to_f16_dual<<<dim3(256, 2), 256>>>(Wk, Wv, wk, wv, DMODEL * DMODEL / 4);
    convert_transpose_w<<<dim3(32, 32), 256>>>(Wq, wqt);

    // 4) G partials: lower-triangle blocks, split-K x2  (288 CTAs)
    gemm_gsym<<<dim3(2, NTRI, BATCH), GEMM_THREADS, GEMM_SMEM>>>(xT, gpart);

    // 5) reduce partials + mirror to full symmetric G
    g_reduce_mirror<<<dim3(NTRI, BATCH), 256>>>(gpart, G);

    // 6) T1_b = Wk @ G_b
    gemm_f16c<__half><<<dim3(8, 8, BATCH), GEMM_THREADS, GEMM_SMEM>>>(
        wk, G, t1, DMODEL, DMODEL, DMODEL, DMODEL / KT, 0, DD, DD);

    // 7-8) kv[b,h] = 0.125 * T1_h @ Wv_h^T   (split-K x8 + reduce)
    kv_from_t1_part<<<dim3(8, HEADS, BATCH), 256>>>(t1, wv, kvp);
    kv_reduce_kernel<<<(BATCH * HEADS * DKH * DKH) / 256, 256>>>(kvp, kv);

    // 9) Zt_b = (kv @ Wo^T) laid out [n][hd]
    zbuild_kernel<<<dim3(DMODEL / 64, HEADS, BATCH), 256>>>(kv, Wo, zt);

    // 10) Pt_b[n][c] = Zt_b @ Wq^T-cols
    gemm_f16c<__half><<<dim3(8, 8, BATCH), GEMM_THREADS, GEMM_SMEM>>>(
        zt, wqt, pt, DMODEL, DMODEL, DMODEL, DMODEL / KT, DD, 0, DD);

    // 11) out_b = x_b @ Pt_b^T  -> fp32
    gemm_f16c<float><<<dim3(8, SEQ / 128, BATCH), GEMM_THREADS, GEMM_SMEM>>>(
        xt, pt, out, DMODEL, DMODEL, DMODEL, DMODEL / KT,
        (size_t)SEQ * DMODEL, DD, (size_t)SEQ * DMODEL);
}

// round 15
// speedup vs baseline: 1.0552x; 1.0552x over previous
#include <cuda_runtime.h>
#include <cuda_fp16.h>
#include <cstdint>

// ----------------------------------------------------------------------------
// LinearMultiHeadAttention, fully reassociated (fp16 mma.sync, fp32 accum):
//   G_b  = x_b^T x_b          (symmetric: 36 lower-tri blocks, split-K x2)
//   T1_b = Wk @ G_b           (GEMM, 1024^3)
//   kv[b,h] = 0.125 * T1_h @ Wv_h^T   (fp32, split-K8 + reduce)
//   Zt_b[n][hd] = sum_e Wo[n][he] kv[b,h,d,e]
//   Pt_b = Zt_b @ Wq_t^T      (GEMM, 1024^3)
//   out_b = x_b @ Pt_b^T      (GEMM, M=4096, N=K=1024, fp32 out)
// R15: mainloop reverted to R12 (best measured; R13/R14 variants were not
//      better — tensor% is ceiling-pinned at ~55%). Non-GEMM attack instead:
//      convert_transpose_x re-tiled 64x64 for full-line coalesced transposed
//      stores; Wk/Wv converts fused into one dual launch.
// ----------------------------------------------------------------------------

static constexpr int BATCH  = 4;
static constexpr int SEQ    = 4096;
static constexpr int DMODEL = 1024;
static constexpr int HEADS  = 16;
static constexpr int DKH    = 64;
static constexpr int NTOK   = BATCH * SEQ;   // 16384
static constexpr int NTRI   = 36;            // lower-triangle 128x128 blocks

// Scratch (__device__ globals; no allocations allowed)
__device__ __half g_xt[NTOK * DMODEL];                 // x fp16 [b][t][c]
__device__ __half g_xT[NTOK * DMODEL];                 // x fp16 [b][c][t]
__device__ __half g_wk[DMODEL * DMODEL];
__device__ __half g_wv[DMODEL * DMODEL];
__device__ __half g_wqt[DMODEL * DMODEL];              // Wq^T [c][hd]
__device__ float  g_gpart[2 * BATCH * NTRI * 128 * 128];   // 18 MB
__device__ __half g_G[BATCH * DMODEL * DMODEL];
__device__ __half g_t1[BATCH * DMODEL * DMODEL];
__device__ float  g_kvp[8 * BATCH * HEADS * DKH * DKH];
__device__ float  g_kv[BATCH * HEADS * DKH * DKH];
__device__ __half g_zt[BATCH * DMODEL * DMODEL];
__device__ __half g_pt[BATCH * DMODEL * DMODEL];

// ------------------------------------------------------------------ helpers --
__device__ __forceinline__ void cp16(uint32_t smem_dst, const void* gmem_src) {
    asm volatile("cp.async.cg.shared.global [%0], [%1], 16;"
                 :: "r"(smem_dst), "l"(gmem_src) : "memory");
}
__device__ __forceinline__ uint32_t smem_u32(const void* p) {
    uint32_t a;
    asm("{ .reg .u64 t; cvta.to.shared.u64 t, %1; cvt.u32.u64 %0, t; }"
        : "=r"(a) : "l"(p));
    return a;
}
__device__ __forceinline__ void ldsm4(uint32_t& r0, uint32_t& r1,
                                      uint32_t& r2, uint32_t& r3,
                                      uint32_t addr) {
    asm volatile("ldmatrix.sync.aligned.m8n8.x4.shared.b16 {%0,%1,%2,%3}, [%4];"
                 : "=r"(r0), "=r"(r1), "=r"(r2), "=r"(r3) : "r"(addr));
}
__device__ __forceinline__ void store_pair(float* C, float a, float b) {
    *(float2*)C = make_float2(a, b);
}
__device__ __forceinline__ void store_pair(__half* C, float a, float b) {
    *(__half2*)C = __floats2half2_rn(a, b);
}

// --------------------------------------------------------------- converts ---
__global__ void f32_to_f16_dual(const float* __restrict__ s0,
                                const float* __restrict__ s1,
                                __half* __restrict__ d0,
                                __half* __restrict__ d1, int n4) {
    const float* s = blockIdx.y ? s1 : s0;
    __half* d = blockIdx.y ? d1 : d0;
    int i = blockIdx.x * blockDim.x + threadIdx.x;
    int stride = gridDim.x * blockDim.x;
    for (; i < n4; i += stride) {
        float4 v = ((const float4*)s)[i];
        __half2* o = (__half2*)d + 2 * (size_t)i;
        o[0] = __floats2half2_rn(v.x, v.y);
        o[1] = __floats2half2_rn(v.z, v.w);
    }
}

// x fp32 [b][t][c] -> xt fp16 [b][t][c] AND xT fp16 [b][c][t]
// 64x64 tiles, 256 threads: both the direct and the transposed stores cover
// 64 contiguous halves = full 128B lines.
__global__ void convert_transpose_x(const float* __restrict__ x,
                                    __half* __restrict__ xt,
                                    __half* __restrict__ xT) {
    __shared__ __half tile[64][65];
    const int c0 = blockIdx.x * 64;
    const int t0 = blockIdx.y * 64;                  // 4096 % 64 == 0
    const int tx = threadIdx.x & 63;
    const int ty = threadIdx.x >> 6;                 // 0..3
    #pragma unroll
    for (int i = 0; i < 16; i++) {
        int t = t0 + ty + i * 4;
        __half h = __float2half_rn(x[(size_t)t * DMODEL + c0 + tx]);
        xt[(size_t)t * DMODEL + c0 + tx] = h;
        tile[ty + i * 4][tx] = h;
    }
    __syncthreads();
    const int b = t0 >> 12;
    const int tl = t0 & 4095;
    #pragma unroll
    for (int i = 0; i < 16; i++) {
        int c = c0 + ty + i * 4;
        xT[((size_t)b * DMODEL + c) * SEQ + tl + tx] = tile[tx][ty + i * 4];
    }
}

// W fp32 [r][c] (1024x1024) -> Wt fp16 [c][r]
__global__ void convert_transpose_w(const float* __restrict__ W,
                                    __half* __restrict__ Wt) {
    __shared__ __half tile[32][33];
    const int c0 = blockIdx.x * 32;
    const int r0 = blockIdx.y * 32;
    const int tx = threadIdx.x & 31;
    const int ty = threadIdx.x >> 5;
    #pragma unroll
    for (int i = 0; i < 4; i++) {
        int r = r0 + ty + i * 8;
        tile[ty + i * 8][tx] = __float2half_rn(W[(size_t)r * DMODEL + c0 + tx]);
    }
    __syncthreads();
    #pragma unroll
    for (int i = 0; i < 4; i++) {
        int c = c0 + ty + i * 8;
        Wt[(size_t)c * DMODEL + r0 + tx] = tile[tx][ty + i * 8];
    }
}

// --------------------------------------------------------- GEMM constants ---
// K-tile 64 halves = 128B rows, SW128 XOR swizzle.
// Stage = A(128x128B) + B(128x128B) = 32768 B; 2 stages = 65536 B dynamic.
static constexpr int KT      = 64;
static constexpr int STG_B   = 32768;
static constexpr int B_OFF   = 16384;
static constexpr int GEMM_SMEM = 2 * STG_B;   // 65536
static constexpr int GEMM_THREADS = 128;      // 4 warps (2x2), warp 64x64

// Mainloop (R12, best measured): CTA 128x128, warp 64x64, K-tile 64,
// 2-stage cp.async, two barriers per K-tile. Fills c[4][8][4].
struct FragAddr {
    uint32_t arow[4], brow[4];
    uint32_t asw[4], bsw[4];
    uint32_t lcolb;
};

#define GEMM_MAINLOOP(Ab, Bb, lda, ldb, nkt)                                   \
    const uint32_t sb = smem_u32(sm);                                          \
    auto prefetch = [&](int kt) {                                              \
        uint32_t stg = sb + (kt & 1) * STG_B;                                  \
        _Pragma("unroll")                                                      \
        for (int i = 0; i < 8; i++) {                                          \
            int idx = tid + i * 128;                                           \
            int row = idx >> 3, cc = idx & 7;                                  \
            uint32_t sw = (uint32_t)(cc * 16) ^ (uint32_t)((row & 7) << 4);    \
            cp16(stg + row * 128 + sw,                                         \
                 (Ab) + (size_t)row * (lda) + kt * KT + cc * 8);               \
            cp16(stg + B_OFF + row * 128 + sw,                                 \
                 (Bb) + (size_t)row * (ldb) + kt * KT + cc * 8);               \
        }                                                                      \
        asm volatile("cp.async.commit_group;" ::: "memory");                   \
    };                                                                         \
    prefetch(0);                                                               \
    prefetch(1);                                                               \
    float c[4][8][4];                                                          \
    _Pragma("unroll")                                                          \
    for (int i = 0; i < 4; i++)                                                \
        _Pragma("unroll")                                                      \
        for (int j = 0; j < 8; j++)                                            \
            _Pragma("unroll")                                                  \
            for (int k = 0; k < 4; k++) c[i][j][k] = 0.f;                      \
    const int lrow = (lane & 7) + ((lane >> 3) & 1) * 8;                       \
    FragAddr fa;                                                               \
    fa.lcolb = (uint32_t)((lane >> 4) * 16);                                   \
    _Pragma("unroll")                                                          \
    for (int fm = 0; fm < 4; fm++) {                                           \
        int r = wm + fm * 16 + lrow;                                           \
        fa.arow[fm] = (uint32_t)(r * 128);                                     \
        fa.asw[fm]  = (uint32_t)((r & 7) << 4);                                \
    }                                                                          \
    _Pragma("unroll")                                                          \
    for (int fp = 0; fp < 4; fp++) {                                           \
        int r = wn + fp * 16 + lrow;                                           \
        fa.brow[fp] = (uint32_t)(B_OFF + r * 128);                             \
        fa.bsw[fp]  = (uint32_t)((r & 7) << 4);                                \
    }                                                                          \
    for (int kt = 0; kt < (nkt); kt++) {                                       \
        if (kt + 1 < (nkt)) asm volatile("cp.async.wait_group 1;" ::: "memory"); \
        else                asm volatile("cp.async.wait_group 0;" ::: "memory"); \
        __syncthreads();                                                       \
        const uint32_t stg = sb + (kt & 1) * STG_B;                            \
        _Pragma("unroll")                                                      \
        for (int ks = 0; ks < 4; ks++) {                                       \
            const uint32_t cb = (uint32_t)(ks * 32) + fa.lcolb;                \
            uint32_t a[4][4], b[8][2];                                         \
            _Pragma("unroll")                                                  \
            for (int fm = 0; fm < 4; fm++)                                     \
                ldsm4(a[fm][0], a[fm][1], a[fm][2], a[fm][3],                  \
                      stg + fa.arow[fm] + (cb ^ fa.asw[fm]));                  \
            _Pragma("unroll")                                                  \
            for (int fp = 0; fp < 4; fp++) {                                   \
                uint32_t t0, t1, t2, t3;                                       \
                ldsm4(t0, t1, t2, t3, stg + fa.brow[fp] + (cb ^ fa.bsw[fp]));  \
                b[2 * fp][0] = t0;      b[2 * fp][1] = t2;                     \
                b[2 * fp + 1][0] = t1;  b[2 * fp + 1][1] = t3;                 \
            }                                                                  \
            _Pragma("unroll")                                                  \
            for (int fm = 0; fm < 4; fm++)                                     \
                _Pragma("unroll")                                              \
                for (int fn = 0; fn < 8; fn++)                                 \
                    asm volatile(                                              \
                        "mma.sync.aligned.m16n8k16.row.col.f32.f16.f16.f32 "   \
                        "{%0,%1,%2,%3},{%4,%5,%6,%7},{%8,%9},{%0,%1,%2,%3};"   \
                        : "+f"(c[fm][fn][0]), "+f"(c[fm][fn][1]),              \
                          "+f"(c[fm][fn][2]), "+f"(c[fm][fn][3])               \
                        : "r"(a[fm][0]), "r"(a[fm][1]),                        \
                          "r"(a[fm][2]), "r"(a[fm][3]),                        \
                          "r"(b[fn][0]), "r"(b[fn][1]));                       \
        }                                                                      \
        __syncthreads();                                                       \
        if (kt + 2 < (nkt)) prefetch(kt + 2);                                  \
    }

// --------------------------------------------------- G = x^T x (sym+splitK) --
__global__ __launch_bounds__(GEMM_THREADS, 2)
void gemm_gsym(const __half* __restrict__ xT, float* __restrict__ gpart) {
    extern __shared__ __half sm[];
    const int tid  = threadIdx.x;
    const int lane = tid & 31;
    const int warp = tid >> 5;
    const int wm   = (warp >> 1) * 64;
    const int wn   = (warp & 1) * 64;

    const int tri = blockIdx.y;
    int bi = 0;
    while ((bi + 1) * (bi + 2) / 2 <= tri) bi++;
    const int bj = tri - bi * (bi + 1) / 2;

    const __half* Ab = xT + ((size_t)blockIdx.z * DMODEL + bi * 128) * SEQ
                          + blockIdx.x * 2048;
    const __half* Bb = xT + ((size_t)blockIdx.z * DMODEL + bj * 128) * SEQ
                          + blockIdx.x * 2048;
    float* Cb = gpart + (((size_t)blockIdx.x * BATCH + blockIdx.z) * NTRI + tri)
                        * (128 * 128);

    GEMM_MAINLOOP(Ab, Bb, SEQ, SEQ, 2048 / KT)

    #pragma unroll
    for (int fm = 0; fm < 4; fm++) {
        int r = wm + fm * 16 + (lane >> 2);
        #pragma unroll
        for (int fn = 0; fn < 8; fn++) {
            int cc = wn + fn * 8 + (lane & 3) * 2;
            store_pair(Cb + (size_t)r * 128 + cc,       c[fm][fn][0], c[fm][fn][1]);
            store_pair(Cb + (size_t)(r + 8) * 128 + cc, c[fm][fn][2], c[fm][fn][3]);
        }
    }
}

// Reduce the 2 K-partials, write G tile and (off-diagonal) its mirror.
__global__ void g_reduce_mirror(const float* __restrict__ gpart,
                                __half* __restrict__ G) {
    const int tri = blockIdx.x, b = blockIdx.y;
    int bi = 0;
    while ((bi + 1) * (bi + 2) / 2 <= tri) bi++;
    const int bj = tri - bi * (bi + 1) / 2;

    const float* p0 = gpart + (((size_t)0 * BATCH + b) * NTRI + tri) * (128 * 128);
    const float* p1 = gpart + (((size_t)1 * BATCH + b) * NTRI + tri) * (128 * 128);
    __half* Gb = G + (size_t)b * DMODEL * DMODEL;

    __shared__ __half tr[32][33];
    const int tid = threadIdx.x;
    const int r  = tid >> 3;
    const int cq = (tid & 7) * 4;

    for (int st = 0; st < 16; st++) {
        const int sr = (st >> 2) * 32, sc = (st & 3) * 32;
        __half h[4];
        #pragma unroll
        for (int i = 0; i < 4; i++) {
            int idx = (sr + r) * 128 + sc + cq + i;
            h[i] = __float2half_rn(p0[idx] + p1[idx]);
        }
        {
            __half* o = Gb + (size_t)(bi * 128 + sr + r) * DMODEL
                            + bj * 128 + sc + cq;
            ((__half2*)o)[0] = __halves2half2(h[0], h[1]);
            ((__half2*)o)[1] = __halves2half2(h[2], h[3]);
        }
        __syncthreads();
        #pragma unroll
        for (int i = 0; i < 4; i++) tr[cq + i][r] = h[i];
        __syncthreads();
        if (bi != bj) {
            __half m0 = tr[r][cq], m1 = tr[r][cq + 1];
            __half m2 = tr[r][cq + 2], m3 = tr[r][cq + 3];
            __half* o = Gb + (size_t)(bj * 128 + sc + r) * DMODEL
                            + bi * 128 + sr + cq;
            ((__half2*)o)[0] = __halves2half2(m0, m1);
            ((__half2*)o)[1] = __halves2half2(m2, m3);
        }
    }
}

// ----------------------------------------------------------- fp16 GEMM ------
template <typename OutT>
__global__ __launch_bounds__(GEMM_THREADS, 2)
void gemm_f16c(const __half* __restrict__ A, const __half* __restrict__ B,
               OutT* __restrict__ C, int lda, int ldb, int ldc, int nkt,
               size_t abatch, size_t bbatch, size_t cbatch) {
    extern __shared__ __half sm[];
    const int tid  = threadIdx.x;
    const int lane = tid & 31;
    const int warp = tid >> 5;
    const int wm   = (warp >> 1) * 64;
    const int wn   = (warp & 1) * 64;
    const int m0   = blockIdx.y * 128;
    const int n0   = blockIdx.x * 128;
    const int zz   = blockIdx.z;

    const __half* Ab = A + zz * abatch + (size_t)m0 * lda;
    const __half* Bb = B + zz * bbatch + (size_t)n0 * ldb;
    OutT*         Cb = C + zz * cbatch;

    GEMM_MAINLOOP(Ab, Bb, lda, ldb, nkt)

    #pragma unroll
    for (int fm = 0; fm < 4; fm++) {
        int r = m0 + wm + fm * 16 + (lane >> 2);
        #pragma unroll
        for (int fn = 0; fn < 8; fn++) {
            int cc = n0 + wn + fn * 8 + (lane & 3) * 2;
            store_pair(Cb + (size_t)r * ldc + cc,       c[fm][fn][0], c[fm][fn][1]);
            store_pair(Cb + (size_t)(r + 8) * ldc + cc, c[fm][fn][2], c[fm][fn][3]);
        }
    }
}

// ----------------------------------------------- kv from T1 (split-K x8) ----
__global__ void kv_from_t1_part(const __half* __restrict__ T1,
                                const __half* __restrict__ Wv,
                                float* __restrict__ kvp) {
    const int ck = blockIdx.x, h = blockIdx.y, b = blockIdx.z;
    const int tid = threadIdx.x;
    __shared__ float t1s[64][36];
    __shared__ float wvs[64][36];

    const int row = tid >> 2;
    const int seg = (tid & 3) * 8;
    const int td  = (tid >> 4) * 4;
    const int te  = (tid & 15) * 4;

    const __half* t1b = T1 + ((size_t)b * DMODEL + h * DKH) * DMODEL;
    const __half* wvb = Wv + (size_t)(h * DKH) * DMODEL;

    float acc[4][4];
    #pragma unroll
    for (int i = 0; i < 4; i++)
        #pragma unroll
        for (int j = 0; j < 4; j++) acc[i][j] = 0.f;

    const int cbeg = ck * 128;
    for (int c0 = cbeg; c0 < cbeg + 128; c0 += 32) {
        #pragma unroll
        for (int u = 0; u < 4; u++) {
            float2 f = __half22float2(
                *(const __half2*)(t1b + (size_t)row * DMODEL + c0 + seg + 2 * u));
            t1s[row][seg + 2 * u]     = f.x;
            t1s[row][seg + 2 * u + 1] = f.y;
            float2 g = __half22float2(
                *(const __half2*)(wvb + (size_t)row * DMODEL + c0 + seg + 2 * u));
            wvs[row][seg + 2 * u]     = g.x;
            wvs[row][seg + 2 * u + 1] = g.y;
        }
        __syncthreads();
        #pragma unroll
        for (int kk = 0; kk < 32; kk++) {
            float a0 = t1s[td + 0][kk], a1 = t1s[td + 1][kk];
            float a2 = t1s[td + 2][kk], a3 = t1s[td + 3][kk];
            float b0 = wvs[te + 0][kk], b1 = wvs[te + 1][kk];
            float b2 = wvs[te + 2][kk], b3 = wvs[te + 3][kk];
            acc[0][0] += a0 * b0; acc[0][1] += a0 * b1;
            acc[0][2] += a0 * b2; acc[0][3] += a0 * b3;
            acc[1][0] += a1 * b0; acc[1][1] += a1 * b1;
            acc[1][2] += a1 * b2; acc[1][3] += a1 * b3;
            acc[2][0] += a2 * b0; acc[2][1] += a2 * b1;
            acc[2][2] += a2 * b2; acc[2][3] += a2 * b3;
            acc[3][0] += a3 * b0; acc[3][1] += a3 * b1;
            acc[3][2] += a3 * b2; acc[3][3] += a3 * b3;
        }
        __syncthreads();
    }

    float* o = kvp + ((size_t)(ck * BATCH * HEADS) + b * HEADS + h) * (DKH * DKH);
    #pragma unroll
    for (int i = 0; i < 4; i++)
        *(float4*)(o + (size_t)(td + i) * DKH + te) =
            make_float4(acc[i][0], acc[i][1], acc[i][2], acc[i][3]);
}

__global__ void kv_reduce_kernel(const float* __restrict__ kvp,
                                 float* __restrict__ kv) {
    int idx = blockIdx.x * blockDim.x + threadIdx.x;
    const size_t stride = (size_t)BATCH * HEADS * DKH * DKH;
    float s = 0.f;
    #pragma unroll
    for (int ck = 0; ck < 8; ck++) s += kvp[ck * stride + idx];
    kv[idx] = s * 0.125f;
}

// -------------------------------------------------------------- Z build -----
__global__ void zbuild_kernel(const float* __restrict__ kv,
                              const float* __restrict__ Wo,
                              __half* __restrict__ zt) {
    const int nb = blockIdx.x, h = blockIdx.y, b = blockIdx.z;
    const int tid = threadIdx.x;
    __shared__ float wos[64][64];
    __shared__ float kvs[64][64];

    {
        const int r = tid >> 2;
        const int c0 = (tid & 3) * 16;
        const float* wsrc = Wo + (size_t)(nb * 64 + r) * DMODEL + h * DKH;
        const float* ksrc = kv + (size_t)((b * HEADS + h) * DKH + r) * DKH;
        #pragma unroll
        for (int i = 0; i < 4; i++) {
            *(float4*)&wos[r][c0 + i * 4] = *(const float4*)(wsrc + c0 + i * 4);
            *(float4*)&kvs[r][c0 + i * 4] = *(const float4*)(ksrc + c0 + i * 4);
        }
    }
    __syncthreads();

    const int tn = (tid >> 4) * 4;
    const int td = (tid & 15) * 4;
    float acc[4][4];
    #pragma unroll
    for (int i = 0; i < 4; i++)
        #pragma unroll
        for (int j = 0; j < 4; j++) acc[i][j] = 0.f;

    for (int e = 0; e < 64; e += 4) {
        float4 w[4], k[4];
        #pragma unroll
        for (int i = 0; i < 4; i++) w[i] = *(const float4*)&wos[tn + i][e];
        #pragma unroll
        for (int j = 0; j < 4; j++) k[j] = *(const float4*)&kvs[td + j][e];
        #pragma unroll
        for (int i = 0; i < 4; i++)
            #pragma unroll
            for (int j = 0; j < 4; j++)
                acc[i][j] += w[i].x * k[j].x + w[i].y * k[j].y +
                             w[i].z * k[j].z + w[i].w * k[j].w;
    }

    #pragma unroll
    for (int i = 0; i < 4; i++) {
        __half* o = zt + (size_t)(b * DMODEL + nb * 64 + tn + i) * DMODEL
                       + h * DKH + td;
        ((__half2*)o)[0] = __floats2half2_rn(acc[i][0], acc[i][1]);
        ((__half2*)o)[1] = __floats2half2_rn(acc[i][2], acc[i][3]);
    }
}

// -------------------------------------------------------------------- launch --
extern "C" void kernel_launch(void* const* d_in, const int* in_sizes, int n_in,
                              void* d_out, int out_size) {
    (void)in_sizes; (void)n_in; (void)out_size;
    const float* x  = (const float*)d_in[0];
    const float* Wq = (const float*)d_in[1];
    const float* Wk = (const float*)d_in[2];
    const float* Wv = (const float*)d_in[3];
    const float* Wo = (const float*)d_in[4];
    float* out = (float*)d_out;

    __half *xt, *xT, *wk, *wv, *wqt, *G, *t1, *zt, *pt;
    float *gpart, *kvp, *kv;
    cudaGetSymbolAddress((void**)&xt,    g_xt);
    cudaGetSymbolAddress((void**)&xT,    g_xT);
    cudaGetSymbolAddress((void**)&wk,    g_wk);
    cudaGetSymbolAddress((void**)&wv,    g_wv);
    cudaGetSymbolAddress((void**)&wqt,   g_wqt);
    cudaGetSymbolAddress((void**)&gpart, g_gpart);
    cudaGetSymbolAddress((void**)&G,     g_G);
    cudaGetSymbolAddress((void**)&t1,    g_t1);
    cudaGetSymbolAddress((void**)&kvp,   g_kvp);
    cudaGetSymbolAddress((void**)&kv,    g_kv);
    cudaGetSymbolAddress((void**)&zt,    g_zt);
    cudaGetSymbolAddress((void**)&pt,    g_pt);

    cudaFuncSetAttribute(gemm_gsym,
                         cudaFuncAttributeMaxDynamicSharedMemorySize, GEMM_SMEM);
    cudaFuncSetAttribute(gemm_f16c<__half>,
                         cudaFuncAttributeMaxDynamicSharedMemorySize, GEMM_SMEM);
    cudaFuncSetAttribute(gemm_f16c<float>,
                         cudaFuncAttributeMaxDynamicSharedMemorySize, GEMM_SMEM);

    const size_t DD = (size_t)DMODEL * DMODEL;

    // 1-3) converts (gsym stays launch #4 for ncu continuity)
    convert_transpose_x<<<dim3(DMODEL / 64, NTOK / 64), 256>>>(x, xt, xT);
    f32_to_f16_dual<<<dim3(256, 2), 256>>>(Wk, Wv, wk, wv, DMODEL * DMODEL / 4);
    convert_transpose_w<<<dim3(32, 32), 256>>>(Wq, wqt);

    // 4) G partials: lower-triangle blocks, split-K x2  (288 CTAs)
    gemm_gsym<<<dim3(2, NTRI, BATCH), GEMM_THREADS, GEMM_SMEM>>>(xT, gpart);

    // 5) reduce partials + mirror to full symmetric G
    g_reduce_mirror<<<dim3(NTRI, BATCH), 256>>>(gpart, G);

    // 6) T1_b = Wk @ G_b
    gemm_f16c<__half><<<dim3(8, 8, BATCH), GEMM_THREADS, GEMM_SMEM>>>(
        wk, G, t1, DMODEL, DMODEL, DMODEL, DMODEL / KT, 0, DD, DD);

    // 7-8) kv[b,h] = 0.125 * T1_h @ Wv_h^T   (split-K x8 + reduce)
    kv_from_t1_part<<<dim3(8, HEADS, BATCH), 256>>>(t1, wv, kvp);
    kv_reduce_kernel<<<(BATCH * HEADS * DKH * DKH) / 256, 256>>>(kvp, kv);

    // 9) Zt_b = (kv @ Wo^T) laid out [n][hd]
    zbuild_kernel<<<dim3(DMODEL / 64, HEADS, BATCH), 256>>>(kv, Wo, zt);

    // 10) Pt_b[n][c] = Zt_b @ Wq^T-cols
    gemm_f16c<__half><<<dim3(8, 8, BATCH), GEMM_THREADS, GEMM_SMEM>>>(
        zt, wqt, pt, DMODEL, DMODEL, DMODEL, DMODEL / KT, DD, 0, DD);

    // 11) out_b = x_b @ Pt_b^T  -> fp32
    gemm_f16c<float><<<dim3(8, SEQ / 128, BATCH), GEMM_THREADS, GEMM_SMEM>>>(
        xt, pt, out, DMODEL, DMODEL, DMODEL, DMODEL / KT,
        (size_t)SEQ * DMODEL, DD, (size_t)SEQ * DMODEL);
}